// round 1
// baseline (speedup 1.0000x reference)
#include <cuda_runtime.h>
#include <cstddef>

#define B_SZ   4
#define T_LEN  512
#define S_LEN  4096
#define HID    1024
#define NH     16
#define HD     64

// Scratch (allocation-free contract: __device__ globals)
__device__ float g_Q[B_SZ * T_LEN * HID];                       // 8 MB
__device__ float g_K[B_SZ * S_LEN * HID];                       // 64 MB
__device__ float g_V[B_SZ * S_LEN * HID];                       // 64 MB
__device__ float g_Wt[(size_t)B_SZ * NH * T_LEN * S_LEN];       // 512 MB scores->weights
__device__ float g_att[B_SZ * T_LEN * HID];                     // 8 MB

// ---------------------------------------------------------------------------
// Generic SGEMM: C[M,N] = A[M,K] @ W[K,N] + bias[N]  (+ seg_emb gather if SEG)
// M % 128 == 0, N % 128 == 0, K % 8 == 0. 128x128 tile, BK=8, double-buffered.
// ---------------------------------------------------------------------------
template<int SEG>
__global__ __launch_bounds__(256, 2)
void gemm_bias_kernel(const float* __restrict__ A, const float* __restrict__ Wm,
                      const float* __restrict__ bias,
                      const int* __restrict__ seg_ids,
                      const float* __restrict__ seg_emb,
                      float* __restrict__ C, int M, int N, int K)
{
    __shared__ float As[2][8][128];
    __shared__ float Bs[2][8][128];
    const int tid  = threadIdx.x;
    const int trow = tid / 16, tcol = tid % 16;
    const int aRow = tid >> 1, aCol = (tid & 1) * 4;
    const int bRow = tid >> 5, bCol = (tid & 31) * 4;
    const float* Ab = A + (size_t)blockIdx.y * 128 * K;
    const float* Wb = Wm + blockIdx.x * 128;

    float acc[8][8] = {};

#define GB_LOAD(kt, bf) do {                                                        \
    float4 av_ = *reinterpret_cast<const float4*>(Ab + (size_t)aRow * K + (kt) + aCol); \
    As[bf][aCol + 0][aRow] = av_.x; As[bf][aCol + 1][aRow] = av_.y;                 \
    As[bf][aCol + 2][aRow] = av_.z; As[bf][aCol + 3][aRow] = av_.w;                 \
    float4 bv_ = *reinterpret_cast<const float4*>(Wb + (size_t)((kt) + bRow) * N + bCol); \
    *reinterpret_cast<float4*>(&Bs[bf][bRow][bCol]) = bv_;                          \
  } while (0)

    GB_LOAD(0, 0);
    __syncthreads();
    int buf = 0;
    for (int kt = 0; kt < K; kt += 8) {
        if (kt + 8 < K) GB_LOAD(kt + 8, buf ^ 1);
        #pragma unroll
        for (int k = 0; k < 8; k++) {
            float rm[8], rn[8];
            #pragma unroll
            for (int i = 0; i < 8; i++) rm[i] = As[buf][k][trow * 8 + i];
            #pragma unroll
            for (int j = 0; j < 8; j++) rn[j] = Bs[buf][k][tcol * 8 + j];
            #pragma unroll
            for (int i = 0; i < 8; i++)
                #pragma unroll
                for (int j = 0; j < 8; j++)
                    acc[i][j] = fmaf(rm[i], rn[j], acc[i][j]);
        }
        __syncthreads();
        buf ^= 1;
    }
#undef GB_LOAD

    #pragma unroll
    for (int i = 0; i < 8; i++) {
        const int m = blockIdx.y * 128 + trow * 8 + i;
        float* Crow = C + (size_t)m * N + blockIdx.x * 128 + tcol * 8;
        const float* br = bias + blockIdx.x * 128 + tcol * 8;
        const float* sr = nullptr;
        if (SEG) sr = seg_emb + (size_t)seg_ids[m] * N + blockIdx.x * 128 + tcol * 8;
        #pragma unroll
        for (int j = 0; j < 8; j += 4) {
            float4 o;
            o.x = acc[i][j + 0] + br[j + 0];
            o.y = acc[i][j + 1] + br[j + 1];
            o.z = acc[i][j + 2] + br[j + 2];
            o.w = acc[i][j + 3] + br[j + 3];
            if (SEG) { o.x += sr[j]; o.y += sr[j + 1]; o.z += sr[j + 2]; o.w += sr[j + 3]; }
            *reinterpret_cast<float4*>(Crow + j) = o;
        }
    }
}

// ---------------------------------------------------------------------------
// Scores: Sc[bh, t, s] = (QK^T)/8 with mask.  Batched over bh = b*NH + h.
// A = Q_bh [T,64] (row stride HID), B = K_bh [S,64] (row stride HID), C = A·B^T
// grid: (S/128, T/128, B*NH), 128x128 tile, BK=8 over d=64, double-buffered
// ---------------------------------------------------------------------------
__global__ __launch_bounds__(256, 2)
void scores_kernel(const float* __restrict__ Q, const float* __restrict__ Kp,
                   const int* __restrict__ amask, float* __restrict__ Sc)
{
    __shared__ float Qs[2][8][128];
    __shared__ float Ks[2][8][128];
    const int bh = blockIdx.z, b = bh / NH, h = bh % NH;
    const int tid  = threadIdx.x;
    const int trow = tid / 16, tcol = tid % 16;
    const int lRow = tid >> 1, lCol = (tid & 1) * 4;
    const float* Qb = Q + (size_t)(b * T_LEN + blockIdx.y * 128) * HID + h * HD;
    const float* Kb = Kp + (size_t)(b * S_LEN + blockIdx.x * 128) * HID + h * HD;
    float acc[8][8] = {};

#define SC_LOAD(kt, bf) do {                                                          \
    float4 qa_ = *reinterpret_cast<const float4*>(Qb + (size_t)lRow * HID + (kt) + lCol); \
    Qs[bf][lCol + 0][lRow] = qa_.x; Qs[bf][lCol + 1][lRow] = qa_.y;                   \
    Qs[bf][lCol + 2][lRow] = qa_.z; Qs[bf][lCol + 3][lRow] = qa_.w;                   \
    float4 ka_ = *reinterpret_cast<const float4*>(Kb + (size_t)lRow * HID + (kt) + lCol); \
    Ks[bf][lCol + 0][lRow] = ka_.x; Ks[bf][lCol + 1][lRow] = ka_.y;                   \
    Ks[bf][lCol + 2][lRow] = ka_.z; Ks[bf][lCol + 3][lRow] = ka_.w;                   \
  } while (0)

    SC_LOAD(0, 0);
    __syncthreads();
    int buf = 0;
    for (int kt = 0; kt < HD; kt += 8) {
        if (kt + 8 < HD) SC_LOAD(kt + 8, buf ^ 1);
        #pragma unroll
        for (int k = 0; k < 8; k++) {
            float rm[8], rn[8];
            #pragma unroll
            for (int i = 0; i < 8; i++) rm[i] = Qs[buf][k][trow * 8 + i];
            #pragma unroll
            for (int j = 0; j < 8; j++) rn[j] = Ks[buf][k][tcol * 8 + j];
            #pragma unroll
            for (int i = 0; i < 8; i++)
                #pragma unroll
                for (int j = 0; j < 8; j++)
                    acc[i][j] = fmaf(rm[i], rn[j], acc[i][j]);
        }
        __syncthreads();
        buf ^= 1;
    }
#undef SC_LOAD

    const int s0 = blockIdx.x * 128 + tcol * 8;
    float* Sb = Sc + (size_t)bh * T_LEN * S_LEN;
    #pragma unroll
    for (int i = 0; i < 8; i++) {
        const int t = blockIdx.y * 128 + trow * 8 + i;
        float* row = Sb + (size_t)t * S_LEN + s0;
        #pragma unroll
        for (int j = 0; j < 8; j++) {
            float v = acc[i][j] * 0.125f;  // 1/sqrt(64)
            if (amask[b * S_LEN + s0 + j] == 0) v = -1e9f;
            row[j] = v;
        }
    }
}

// ---------------------------------------------------------------------------
// Row softmax over s (4096), one block per (bh, t) row. Register-resident.
// ---------------------------------------------------------------------------
__global__ __launch_bounds__(256)
void softmax_kernel(float* __restrict__ Wt)
{
    float* row = Wt + (size_t)blockIdx.x * S_LEN;
    const int tid = threadIdx.x;
    __shared__ float red[8];

    float v[16];
    #pragma unroll
    for (int i = 0; i < 16; i++) v[i] = row[tid + i * 256];

    float m = -1e30f;
    #pragma unroll
    for (int i = 0; i < 16; i++) m = fmaxf(m, v[i]);
    #pragma unroll
    for (int o = 16; o; o >>= 1) m = fmaxf(m, __shfl_xor_sync(0xFFFFFFFFu, m, o));
    if ((tid & 31) == 0) red[tid >> 5] = m;
    __syncthreads();
    float gmax = red[0];
    #pragma unroll
    for (int w = 1; w < 8; w++) gmax = fmaxf(gmax, red[w]);
    __syncthreads();

    float s = 0.f;
    #pragma unroll
    for (int i = 0; i < 16; i++) { v[i] = expf(v[i] - gmax); s += v[i]; }
    #pragma unroll
    for (int o = 16; o; o >>= 1) s += __shfl_xor_sync(0xFFFFFFFFu, s, o);
    if ((tid & 31) == 0) red[tid >> 5] = s;
    __syncthreads();
    float tot = red[0];
    #pragma unroll
    for (int w = 1; w < 8; w++) tot += red[w];

    const float inv = 1.0f / tot;
    #pragma unroll
    for (int i = 0; i < 16; i++) row[tid + i * 256] = v[i] * inv;
}

// ---------------------------------------------------------------------------
// provenance[b,t,s] = mean over heads of weights
// ---------------------------------------------------------------------------
__global__ __launch_bounds__(256)
void provenance_kernel(const float* __restrict__ Wt, float* __restrict__ out)
{
    const size_t idx = (size_t)blockIdx.x * 256 + threadIdx.x;  // over B*T*S
    const int s = (int)(idx & (S_LEN - 1));
    const int t = (int)((idx >> 12) & (T_LEN - 1));
    const int b = (int)(idx >> 21);
    float sum = 0.f;
    #pragma unroll
    for (int h = 0; h < NH; h++)
        sum += Wt[((size_t)(b * NH + h) * T_LEN + t) * S_LEN + s];
    out[idx] = sum * (1.0f / NH);
}

// ---------------------------------------------------------------------------
// attended[b,t,h,d] = sum_s W[bh,t,s] * V[b,s,h*64+d]
// Batched GEMM per bh: [T,S] @ [S,64]. 64x64 tile, BK=32.
// grid: (T/64, B*NH), 256 threads, 4x4 micro-tile.
// ---------------------------------------------------------------------------
__global__ __launch_bounds__(256, 2)
void attended_kernel(const float* __restrict__ Wt, const float* __restrict__ V,
                     float* __restrict__ att)
{
    __shared__ float Ps[32][65];  // Ps[k][m]
    __shared__ float Vs[32][65];  // Vs[k][n]
    const int bh = blockIdx.y, b = bh / NH, h = bh % NH;
    const int tid  = threadIdx.x;
    const int trow = tid / 16, tcol = tid % 16;
    const float* Wb = Wt + (size_t)bh * T_LEN * S_LEN + (size_t)blockIdx.x * 64 * S_LEN;
    const float* Vb = V + (size_t)b * S_LEN * HID + h * HD;
    float acc[4][4] = {};

    const int aR = tid >> 3;        // 0..31 (row of W tile)
    const int aC = (tid & 7) * 4;   // 0..28 (k within chunk)
    const int bR = tid >> 4;        // 0..15 (k row of V tile)
    const int bC = (tid & 15) * 4;  // 0..60 (n)

    for (int kt = 0; kt < S_LEN; kt += 32) {
        #pragma unroll
        for (int u = 0; u < 2; u++) {
            const int r = aR + u * 32;
            float4 a = *reinterpret_cast<const float4*>(Wb + (size_t)r * S_LEN + kt + aC);
            Ps[aC + 0][r] = a.x; Ps[aC + 1][r] = a.y;
            Ps[aC + 2][r] = a.z; Ps[aC + 3][r] = a.w;
        }
        #pragma unroll
        for (int u = 0; u < 2; u++) {
            const int r = bR + u * 16;
            float4 vv = *reinterpret_cast<const float4*>(Vb + (size_t)(kt + r) * HID + bC);
            Vs[r][bC + 0] = vv.x; Vs[r][bC + 1] = vv.y;
            Vs[r][bC + 2] = vv.z; Vs[r][bC + 3] = vv.w;
        }
        __syncthreads();
        #pragma unroll
        for (int k = 0; k < 32; k++) {
            float rm[4], rn[4];
            #pragma unroll
            for (int i = 0; i < 4; i++) rm[i] = Ps[k][trow * 4 + i];
            #pragma unroll
            for (int j = 0; j < 4; j++) rn[j] = Vs[k][tcol * 4 + j];
            #pragma unroll
            for (int i = 0; i < 4; i++)
                #pragma unroll
                for (int j = 0; j < 4; j++)
                    acc[i][j] = fmaf(rm[i], rn[j], acc[i][j]);
        }
        __syncthreads();
    }

    #pragma unroll
    for (int i = 0; i < 4; i++) {
        const int t = blockIdx.x * 64 + trow * 4 + i;
        float* arow = att + (size_t)(b * T_LEN + t) * HID + h * HD + tcol * 4;
        float4 o = { acc[i][0], acc[i][1], acc[i][2], acc[i][3] };
        *reinterpret_cast<float4*>(arow) = o;
    }
}

// ---------------------------------------------------------------------------
extern "C" void kernel_launch(void* const* d_in, const int* in_sizes, int n_in,
                              void* d_out, int out_size)
{
    const float* query  = (const float*)d_in[0];
    const float* key    = (const float*)d_in[1];
    const float* value  = (const float*)d_in[2];
    const int*   amask  = (const int*)d_in[3];
    const int*   segids = (const int*)d_in[4];
    const float* Wq = (const float*)d_in[5];
    const float* bq = (const float*)d_in[6];
    const float* Wk = (const float*)d_in[7];
    const float* bk = (const float*)d_in[8];
    const float* Wv = (const float*)d_in[9];
    const float* bv = (const float*)d_in[10];
    const float* Wo = (const float*)d_in[11];
    const float* bo = (const float*)d_in[12];
    const float* seg_emb = (const float*)d_in[13];
    float* out = (float*)d_out;

    float *Qp, *Kp, *Vp, *Wt, *att;
    cudaGetSymbolAddress((void**)&Qp,  g_Q);
    cudaGetSymbolAddress((void**)&Kp,  g_K);
    cudaGetSymbolAddress((void**)&Vp,  g_V);
    cudaGetSymbolAddress((void**)&Wt,  g_Wt);
    cudaGetSymbolAddress((void**)&att, g_att);

    const int MQ = B_SZ * T_LEN;   // 2048
    const int MK = B_SZ * S_LEN;   // 16384

    // Projections
    gemm_bias_kernel<0><<<dim3(HID / 128, MQ / 128), 256>>>(query, Wq, bq, nullptr, nullptr, Qp, MQ, HID, HID);
    gemm_bias_kernel<1><<<dim3(HID / 128, MK / 128), 256>>>(key,   Wk, bk, segids, seg_emb, Kp, MK, HID, HID);
    gemm_bias_kernel<0><<<dim3(HID / 128, MK / 128), 256>>>(value, Wv, bv, nullptr, nullptr, Vp, MK, HID, HID);

    // Attention
    scores_kernel<<<dim3(S_LEN / 128, T_LEN / 128, B_SZ * NH), 256>>>(Qp, Kp, amask, Wt);
    softmax_kernel<<<B_SZ * NH * T_LEN, 256>>>(Wt);
    provenance_kernel<<<(B_SZ * T_LEN * S_LEN) / 256, 256>>>(Wt, out + (size_t)B_SZ * T_LEN * HID);
    attended_kernel<<<dim3(T_LEN / 64, B_SZ * NH), 256>>>(Wt, Vp, att);

    // Output projection -> first segment of d_out
    gemm_bias_kernel<0><<<dim3(HID / 128, MQ / 128), 256>>>(att, Wo, bo, nullptr, nullptr, out, MQ, HID, HID);
}